// round 4
// baseline (speedup 1.0000x reference)
#include <cuda_runtime.h>
#include <cuda_bf16.h>
#include <math.h>

// HMM forward: 511 serial steps of batched log-space matvec.
// Single persistent kernel. 16 clusters x 8 CTAs; cluster owns 4 batches,
// CTA owns a 64-row slice of W (fp32, resident in smem all 511 steps).
// W = (A^T + eps)/(colmax + eps) built in-kernel (== exp(logA_T - rowmax)).
// Stabilization max is per-CTA (exact: it cancels in log(z)+amax).

#define HH 512
#define VV 50257
#define BB 64
#define TT 512
#define NT 512        // threads per CTA (16 warps)

using ull = unsigned long long;

// only global scratch: double-buffered alpha state exchanged through L2
__device__ float g_Alpha[2][BB * HH];

#define CLUSTER_SYNC() do { \
  asm volatile("barrier.cluster.arrive.aligned;" ::: "memory"); \
  asm volatile("barrier.cluster.wait.aligned;"   ::: "memory"); \
} while (0)

__device__ __forceinline__ ull ffma2(ull a, ull b, ull c) {
  ull d;
  asm("fma.rn.f32x2 %0, %1, %2, %3;" : "=l"(d) : "l"(a), "l"(b), "l"(c));
  return d;
}

__device__ __forceinline__ float psum2(ull u) {
  float lo = __uint_as_float((unsigned)u);
  float hi = __uint_as_float((unsigned)(u >> 32));
  return lo + hi;
}

extern __shared__ float sW[];  // 32768 floats = 128KB: Wp[kp:256][r:64][2]

__global__ void __cluster_dims__(8, 1, 1) __launch_bounds__(NT, 1)
hmm_main(const float* __restrict__ A, const float* __restrict__ beta,
         const float* __restrict__ gamma, const int* __restrict__ ids,
         float* __restrict__ out) {
  __shared__ __align__(16) float2 xs[256][4]; // xs[kp][b] = (x[2kp], x[2kp+1])
  __shared__ float4 red[16 * 64];             // red[warp][r] = 4-batch partials
  __shared__ int    sids[4][TT];
  __shared__ float  swmax[64];
  __shared__ float  sAinv[64];
  __shared__ float  smax2[16];

  const int tid  = threadIdx.x;
  const int hs   = blockIdx.x & 7;    // slice == cluster cta rank
  const int bg   = blockIdx.x >> 3;   // batch group
  const int base = hs * 64;

  // ---- in-kernel prologue: colmax of A's slice columns, then W into smem ----
  {
    float* pm = (float*)red;          // reuse red as 8x64 scratch
    int q = tid >> 6, c = tid & 63;
    float m = 0.0f;
    for (int j = q; j < HH; j += 8) m = fmaxf(m, A[j * HH + base + c]);
    pm[q * 64 + c] = m;
    __syncthreads();
    if (tid < 64) {
      float mm = pm[tid];
      #pragma unroll
      for (int q2 = 1; q2 < 8; q2++) mm = fmaxf(mm, pm[q2 * 64 + tid]);
      float d = mm + 1e-12f;
      sAinv[tid] = 1.0f / d;
      swmax[tid] = logf(d);
    }
    __syncthreads();
    for (int idx = tid; idx < 64 * HH; idx += NT) {
      int c2 = idx & 63, j = idx >> 6;
      float v = (A[j * HH + base + c2] + 1e-12f) * sAinv[c2];
      sW[(j >> 1) * 128 + c2 * 2 + (j & 1)] = v;
    }
    for (int i = tid; i < 4 * TT; i += NT) {
      int b0 = i >> 9, t0 = i & (TT - 1);
      sids[b0][t0] = ids[(bg * 4 + b0) * TT + t0];
    }
  }
  __syncthreads();

  const bool active = tid < 256;          // scalar-phase mapping
  const int b     = (tid >> 6) & 3;       // batch 0..3
  const int r     = tid & 63;             // row-in-slice 0..63
  const int h     = base + r;
  const int bglob = bg * 4 + b;
  const int warp  = tid >> 5, lane = tid & 31;

  // ---- init: alpha0 = log(gamma) + beta[:, ids[:,0]] ----
  if (active) {
    float a0 = __logf(gamma[h]) + __ldg(&beta[(size_t)h * VV + sids[b][0]]);
    __stcg(&g_Alpha[0][bglob * HH + h], a0);
  }
  CLUSTER_SYNC();

  int p = 0;
  for (int t = 1; t < TT; t++) {
    // ---- phase 1a: gather beta early; load full alpha; per-CTA batch max ----
    float bsel = 0.0f, amax = 0.0f, av[8];
    if (active) {
      bsel = __ldg(&beta[(size_t)h * VV + sids[b][t]]);  // used ~2K cyc later
      float lmax = -3.4e38f;
      #pragma unroll
      for (int i = 0; i < 8; i++) {
        av[i] = __ldcg(&g_Alpha[p][bglob * HH + i * 64 + r]);
        lmax = fmaxf(lmax, av[i]);
      }
      #pragma unroll
      for (int o = 16; o > 0; o >>= 1)
        lmax = fmaxf(lmax, __shfl_xor_sync(0xffffffffu, lmax, o));
      if (lane == 0) smax2[warp] = lmax;
    }
    __syncthreads();
    // ---- phase 1b: exp-shift and pack x ----
    if (active) {
      amax = fmaxf(smax2[2 * b], smax2[2 * b + 1]);
      #pragma unroll
      for (int i = 0; i < 8; i++) {
        int k = i * 64 + r;
        ((float*)xs)[(k >> 1) * 8 + b * 2 + (k & 1)] = __expf(av[i] - amax);
      }
    }
    __syncthreads();

    // ---- phase 2: matvec, 16 warps; warp owns kp-range [warp*16, warp*16+16)
    ull acc0 = 0, acc1 = 0, acc2 = 0, acc3 = 0,
        acc4 = 0, acc5 = 0, acc6 = 0, acc7 = 0;
    {
      const ull* wp        = (const ull*)sW + warp * (16 * 64) + lane;
      const ulonglong2* xp = (const ulonglong2*)xs + warp * 16 * 2;
      #pragma unroll
      for (int kpi = 0; kpi < 16; kpi++) {
        ull w0 = wp[0];
        ull w1 = wp[32];
        ulonglong2 xa = xp[0];   // batches 0,1 (warp-uniform broadcast)
        ulonglong2 xb = xp[1];   // batches 2,3
        wp += 64; xp += 2;
        acc0 = ffma2(w0, xa.x, acc0);
        acc1 = ffma2(w0, xa.y, acc1);
        acc2 = ffma2(w0, xb.x, acc2);
        acc3 = ffma2(w0, xb.y, acc3);
        acc4 = ffma2(w1, xa.x, acc4);
        acc5 = ffma2(w1, xa.y, acc5);
        acc6 = ffma2(w1, xb.x, acc6);
        acc7 = ffma2(w1, xb.y, acc7);
      }
    }
    red[warp * 64 + lane]      = make_float4(psum2(acc0), psum2(acc1), psum2(acc2), psum2(acc3));
    red[warp * 64 + lane + 32] = make_float4(psum2(acc4), psum2(acc5), psum2(acc6), psum2(acc7));
    __syncthreads();

    // ---- phase 3: reduce 16 k-chunk partials, log, emit ----
    if (active) {
      const float* redf = (const float*)red;
      float z = 0.0f;
      #pragma unroll
      for (int w = 0; w < 16; w++) z += redf[(w * 64 + r) * 4 + b];
      float anew = __logf(z) + amax + swmax[r] + bsel;
      if (t == TT - 1) out[bglob * HH + h] = anew;
      else             __stcg(&g_Alpha[p ^ 1][bglob * HH + h], anew);
    }
    if (t < TT - 1) CLUSTER_SYNC();   // one cluster barrier per step
    p ^= 1;
  }
}

extern "C" void kernel_launch(void* const* d_in, const int* in_sizes, int n_in,
                              void* d_out, int out_size) {
  const float* A     = (const float*)d_in[0];   // alpha_exp (H,H)
  const float* beta  = (const float*)d_in[1];   // (H,V)
  const float* gamma = (const float*)d_in[2];   // (1,H)
  const int*   ids   = (const int*)d_in[3];     // (B,T) int32
  float* out = (float*)d_out;                   // (B,H) f32

  cudaFuncSetAttribute(hmm_main, cudaFuncAttributeMaxDynamicSharedMemorySize,
                       132 * 1024);
  hmm_main<<<128, NT, 131072>>>(A, beta, gamma, ids, out);
}